// round 1
// baseline (speedup 1.0000x reference)
#include <cuda_runtime.h>
#include <cfloat>

#define DIM   256
#define KCB   8192
#define NTOT  32768
#define BM    128
#define BN    128
#define BK    32
#define ESL   33          // es row stride (pad: conflict-free scalar ld/st)
#define NCTA  (NTOT / BM) // 256

__device__ int   g_best[NTOT];
__device__ float g_esq[KCB];

// ---------------------------------------------------------------------------
// Kernel 1: e_sq[k] = sum_c embed[k][c]^2   (one warp per code)
// ---------------------------------------------------------------------------
__global__ void esq_kernel(const float* __restrict__ embed) {
    int k    = blockIdx.x;
    int lane = threadIdx.x;
    const float4* row = (const float4*)(embed + (size_t)k * DIM);
    float s = 0.f;
#pragma unroll
    for (int t = 0; t < 2; ++t) {
        float4 v = row[lane + 32 * t];
        s += v.x * v.x + v.y * v.y + v.z * v.z + v.w * v.w;
    }
#pragma unroll
    for (int o = 16; o; o >>= 1) s += __shfl_xor_sync(0xffffffffu, s, o);
    if (lane == 0) g_esq[k] = s;
}

// ---------------------------------------------------------------------------
// Kernel 2: per row n, best_k = argmin_k ( e_sq[k] - 2 * dot(x_n, e_k) )
// CTA: BM=128 rows (x tile resident in smem), streams all 8192 codes in
// BN=128 chunks, C accumulated in BK=32 chunks. 8x8 microtile per thread,
// strided row/col assignment for conflict-free scalar LDS.
// ---------------------------------------------------------------------------
extern __shared__ float smem[];

__global__ __launch_bounds__(256, 1)
void argmin_kernel(const float* __restrict__ x, const float* __restrict__ embed) {
    float* xs      = smem;                    // BM*DIM            (128 KB)
    float* es      = xs + BM * DIM;           // BN*ESL            (16.5 KB)
    float* esq_s   = es + BN * ESL;           // BN
    float* red_val = esq_s + BN;              // BM*16
    int*   red_idx = (int*)(red_val + BM * 16);

    const int tid = threadIdx.x;
    const int ty  = tid >> 4;                 // 0..15
    const int tx  = tid & 15;                 // 0..15
    const int row0 = blockIdx.x * BM;

    // --- load resident x tile (vectorized, layout matches global) ---
    {
        const float4* gx  = (const float4*)(x + (size_t)row0 * DIM);
        float4*       xs4 = (float4*)xs;
#pragma unroll
        for (int t = 0; t < (BM * DIM / 4) / 256; ++t)
            xs4[tid + 256 * t] = gx[tid + 256 * t];
    }

    float best_val[8];
    int   best_idx[8];
#pragma unroll
    for (int i = 0; i < 8; ++i) { best_val[i] = FLT_MAX; best_idx[i] = 0; }

    for (int nblk = 0; nblk < KCB / BN; ++nblk) {
        const int code0 = nblk * BN;
        float acc[8][8];
#pragma unroll
        for (int i = 0; i < 8; ++i)
#pragma unroll
            for (int j = 0; j < 8; ++j) acc[i][j] = 0.f;

        for (int cb = 0; cb < DIM / BK; ++cb) {
            __syncthreads();   // es/esq_s consumed by previous iteration
            // load embed tile [BN codes x BK dims] transposed-ish into es[col*ESL + c]
#pragma unroll
            for (int l = 0; l < 4; ++l) {
                int lin = tid + l * 256;           // 0..1023
                int col = lin >> 3;                // code within chunk
                int q   = lin & 7;                 // float4 index along C
                float4 v = *(const float4*)(embed + (size_t)(code0 + col) * DIM
                                            + cb * BK + q * 4);
                es[col * ESL + q * 4 + 0] = v.x;
                es[col * ESL + q * 4 + 1] = v.y;
                es[col * ESL + q * 4 + 2] = v.z;
                es[col * ESL + q * 4 + 3] = v.w;
            }
            if (cb == 0 && tid < BN) esq_s[tid] = g_esq[code0 + tid];
            __syncthreads();

            const float* xbase = xs + cb * BK;
#pragma unroll
            for (int kk = 0; kk < BK; ++kk) {
                float xr[8], er[8];
#pragma unroll
                for (int i = 0; i < 8; ++i) xr[i] = xbase[(ty + 16 * i) * DIM + kk];
#pragma unroll
                for (int j = 0; j < 8; ++j) er[j] = es[(tx + 16 * j) * ESL + kk];
#pragma unroll
                for (int i = 0; i < 8; ++i)
#pragma unroll
                    for (int j = 0; j < 8; ++j)
                        acc[i][j] = fmaf(xr[i], er[j], acc[i][j]);
            }
        }

        // --- epilogue: fold this 128-code chunk into per-row running argmin ---
#pragma unroll
        for (int j = 0; j < 8; ++j) {
            int   code = code0 + tx + 16 * j;
            float esq  = esq_s[tx + 16 * j];
#pragma unroll
            for (int i = 0; i < 8; ++i) {
                float d = esq - 2.0f * acc[i][j];
                if (d < best_val[i] || (d == best_val[i] && code < best_idx[i])) {
                    best_val[i] = d;
                    best_idx[i] = code;
                }
            }
        }
    }

    // --- reduce across the 16 tx threads sharing each row ---
    __syncthreads();
#pragma unroll
    for (int i = 0; i < 8; ++i) {
        int r = ty + 16 * i;
        red_val[r * 16 + tx] = best_val[i];
        red_idx[r * 16 + tx] = best_idx[i];
    }
    __syncthreads();
    if (tid < BM) {
        float bv = red_val[tid * 16];
        int   bi = red_idx[tid * 16];
#pragma unroll
        for (int t = 1; t < 16; ++t) {
            float v  = red_val[tid * 16 + t];
            int   ix = red_idx[tid * 16 + t];
            if (v < bv || (v == bv && ix < bi)) { bv = v; bi = ix; }
        }
        g_best[row0 + tid] = bi;
    }
}

// ---------------------------------------------------------------------------
// Kernel 3: out[n] = embed[best[n]]
// ---------------------------------------------------------------------------
__global__ void gather_kernel(const float* __restrict__ embed, float* __restrict__ out) {
    int row = blockIdx.x;
    int idx = g_best[row];
    const float4* src = (const float4*)(embed + (size_t)idx * DIM);
    float4*       dst = (float4*)(out + (size_t)row * DIM);
    dst[threadIdx.x] = src[threadIdx.x];
}

// ---------------------------------------------------------------------------
extern "C" void kernel_launch(void* const* d_in, const int* in_sizes, int n_in,
                              void* d_out, int out_size) {
    const float* x     = (const float*)d_in[0];   // (B*T, 256) fp32
    const float* embed = (const float*)d_in[1];   // (8192, 256) fp32
    float*       out   = (float*)d_out;           // (B*T, 256) fp32

    size_t smem_bytes =
        (size_t)(BM * DIM + BN * ESL + BN + BM * 16) * sizeof(float)
        + (size_t)(BM * 16) * sizeof(int);        // 164,864 B

    cudaFuncSetAttribute(argmin_kernel,
                         cudaFuncAttributeMaxDynamicSharedMemorySize,
                         (int)smem_bytes);

    esq_kernel<<<KCB, 32>>>(embed);
    argmin_kernel<<<NCTA, 256, smem_bytes>>>(x, embed);
    gather_kernel<<<NTOT, 64>>>(embed, out);
}

// round 5
// speedup vs baseline: 3.8216x; 3.8216x over previous
#include <cuda_runtime.h>
#include <cuda_fp16.h>
#include <cfloat>
#include <cstdint>

#define DIM   256
#define KCB   8192
#define NTOT  32768
#define BM    128
#define BN    128
#define MARGIN 0.5f

#define XSTR  264                      // padded half stride (conflict-free ldmatrix)
#define ES_BUF_BYTES (128 * XSTR * 2)
#define MAIN_SMEM (3 * 128 * XSTR * 2) // xs + 2 es buffers = 202752 B

// ---------------- device scratch ----------------
__device__ __align__(16) __half g_xh[NTOT * DIM];
__device__ __align__(16) __half g_eh[KCB * DIM];
__device__ float g_esq[KCB];
__device__ int   g_best[NTOT];
__device__ int   g_flag[NTOT];
__device__ unsigned long long g_bestkey[NTOT];
__device__ int   g_nflag;

extern __shared__ char dynsmem[];

__device__ __forceinline__ uint32_t smem_u32(const void* p) {
    uint32_t a;
    asm("{ .reg .u64 t; cvta.to.shared.u64 t, %1; cvt.u32.u64 %0, t; }" : "=r"(a) : "l"(p));
    return a;
}
__device__ __forceinline__ void cpa16(uint32_t dst, const void* src) {
    asm volatile("cp.async.cg.shared.global [%0], [%1], 16;" :: "r"(dst), "l"(src));
}
#define CP_COMMIT() asm volatile("cp.async.commit_group;" ::: "memory")
#define CP_WAIT1()  asm volatile("cp.async.wait_group 1;" ::: "memory")

__device__ __forceinline__ void ldmx4(uint32_t& r0, uint32_t& r1, uint32_t& r2, uint32_t& r3,
                                      uint32_t addr) {
    asm volatile("ldmatrix.sync.aligned.m8n8.x4.shared.b16 {%0,%1,%2,%3}, [%4];"
                 : "=r"(r0), "=r"(r1), "=r"(r2), "=r"(r3) : "r"(addr));
}
__device__ __forceinline__ void mma16816(float* c, const uint32_t* a, const uint32_t* b) {
    asm volatile("mma.sync.aligned.m16n8k16.row.col.f32.f16.f16.f32 "
                 "{%0,%1,%2,%3}, {%4,%5,%6,%7}, {%8,%9}, {%0,%1,%2,%3};"
                 : "+f"(c[0]), "+f"(c[1]), "+f"(c[2]), "+f"(c[3])
                 : "r"(a[0]), "r"(a[1]), "r"(a[2]), "r"(a[3]), "r"(b[0]), "r"(b[1]));
}
__device__ __forceinline__ unsigned long long mkkey(float f, int idx) {
    unsigned u = __float_as_uint(f);
    u = (u & 0x80000000u) ? ~u : (u | 0x80000000u);
    return ((unsigned long long)u << 32) | (unsigned)idx;
}

// ---------------------------------------------------------------------------
// fp32 -> fp16 conversion of x and embed; reset flag counter
// ---------------------------------------------------------------------------
__global__ void split_kernel(const float* __restrict__ x, const float* __restrict__ embed) {
    if (blockIdx.x == 0 && threadIdx.x == 0) g_nflag = 0;
    const int T1 = NTOT * DIM / 4, T2 = KCB * DIM / 4;
    int stride = gridDim.x * blockDim.x;
    for (int i = blockIdx.x * blockDim.x + threadIdx.x; i < T1 + T2; i += stride) {
        const float4* src; __half2* dst; int j;
        if (i < T1) { src = (const float4*)x;     dst = (__half2*)g_xh; j = i; }
        else        { src = (const float4*)embed; dst = (__half2*)g_eh; j = i - T1; }
        float4 v = src[j];
        dst[2 * j]     = __floats2half2_rn(v.x, v.y);
        dst[2 * j + 1] = __floats2half2_rn(v.z, v.w);
    }
}

__global__ void esq_kernel(const float* __restrict__ embed) {
    int k = blockIdx.x, lane = threadIdx.x;
    const float4* row = (const float4*)(embed + (size_t)k * DIM);
    float s = 0.f;
#pragma unroll
    for (int t = 0; t < 2; ++t) {
        float4 v = row[lane + 32 * t];
        s += v.x * v.x + v.y * v.y + v.z * v.z + v.w * v.w;
    }
#pragma unroll
    for (int o = 16; o; o >>= 1) s += __shfl_xor_sync(0xffffffffu, s, o);
    if (lane == 0) g_esq[k] = s;
}

// ---------------------------------------------------------------------------
// main: fp16 mma.sync argmin with top-2 margin flagging
// ---------------------------------------------------------------------------
__global__ __launch_bounds__(256, 1) void argmin_hmma() {
    const uint32_t sb    = smem_u32(dynsmem);
    const uint32_t sb_xs = sb;
    const uint32_t sb_es = sb + 128 * XSTR * 2;

    const int tid = threadIdx.x;
    const int wid = tid >> 5, l = tid & 31;
    const int warp_m = wid >> 2, warp_n = wid & 3;
    const int row0 = blockIdx.x * BM;

    // ---- prologue: stage xs + es chunks 0,1 via cp.async (FULL 256 halfs/row) ----
#pragma unroll
    for (int t = 0; t < 16; ++t) {                    // xs: 128 rows x 32 segs
        int lin = t * 256 + tid;
        int row = lin >> 5, seg = lin & 31;
        cpa16(sb_xs + (row * XSTR + seg * 8) * 2,
              g_xh + (size_t)(row0 + row) * DIM + seg * 8);
    }
#pragma unroll
    for (int t = 0; t < 16; ++t) {                    // es chunk 0 -> buf 0
        int lin = t * 256 + tid;
        int row = lin >> 5, seg = lin & 31;
        cpa16(sb_es + (row * XSTR + seg * 8) * 2,
              g_eh + (size_t)row * DIM + seg * 8);
    }
    CP_COMMIT();
#pragma unroll
    for (int t = 0; t < 16; ++t) {                    // es chunk 1 -> buf 1
        int lin = t * 256 + tid;
        int row = lin >> 5, seg = lin & 31;
        cpa16(sb_es + ES_BUF_BYTES + (row * XSTR + seg * 8) * 2,
              g_eh + (size_t)(128 + row) * DIM + seg * 8);
    }
    CP_COMMIT();

    // per-lane ldmatrix base addresses
    uint32_t a_base[4];
#pragma unroll
    for (int mi = 0; mi < 4; ++mi)
        a_base[mi] = sb_xs + ((warp_m * 64 + mi * 16 + (l & 15)) * XSTR + (l >> 4) * 8) * 2;
    const int bcode = (l & 7) + ((l >> 4) << 3);
    const int bkh   = (l >> 3) & 1;
    uint32_t b_base[2];
#pragma unroll
    for (int bt = 0; bt < 2; ++bt)
        b_base[bt] = sb_es + ((warp_n * 32 + bt * 16 + bcode) * XSTR + bkh * 8) * 2;

    float acc[4][4][4];
#pragma unroll
    for (int mi = 0; mi < 4; ++mi)
#pragma unroll
        for (int ni = 0; ni < 4; ++ni)
#pragma unroll
            for (int r = 0; r < 4; ++r) acc[mi][ni][r] = 0.f;

    float bv[8], sv[8];
    int   bi[8];
#pragma unroll
    for (int r = 0; r < 8; ++r) { bv[r] = FLT_MAX; sv[r] = FLT_MAX; bi[r] = 0; }

    for (int c = 0; c < KCB / BN; ++c) {
        CP_WAIT1();
        __syncthreads();
        const uint32_t bofs = (c & 1) ? ES_BUF_BYTES : 0;

#pragma unroll 8
        for (int kk = 0; kk < 16; ++kk) {
            uint32_t a[4][4], b[2][4];
#pragma unroll
            for (int mi = 0; mi < 4; ++mi)
                ldmx4(a[mi][0], a[mi][1], a[mi][2], a[mi][3], a_base[mi] + kk * 32);
#pragma unroll
            for (int bt = 0; bt < 2; ++bt)
                ldmx4(b[bt][0], b[bt][1], b[bt][2], b[bt][3], b_base[bt] + bofs + kk * 32);
#pragma unroll
            for (int mi = 0; mi < 4; ++mi) {
#pragma unroll
                for (int ni = 0; ni < 4; ++ni) {
                    uint32_t bf[2] = { b[ni >> 1][(ni & 1) * 2], b[ni >> 1][(ni & 1) * 2 + 1] };
                    mma16816(acc[mi][ni], a[mi], bf);
                }
            }
        }
        __syncthreads();
        if (c + 2 < KCB / BN) {                       // prefetch chunk c+2 (FULL rows)
#pragma unroll
            for (int t = 0; t < 16; ++t) {
                int lin = t * 256 + tid;
                int row = lin >> 5, seg = lin & 31;
                cpa16(sb_es + bofs + (row * XSTR + seg * 8) * 2,
                      g_eh + (size_t)((c + 2) * 128 + row) * DIM + seg * 8);
            }
        }
        CP_COMMIT();

        // ---- epilogue: distances + top-2 ----
        const int colbase = c * 128 + warp_n * 32 + (l & 3) * 2;
#pragma unroll
        for (int ni = 0; ni < 4; ++ni) {
            float2 eq = __ldg((const float2*)(g_esq + colbase + ni * 8));
#pragma unroll
            for (int mi = 0; mi < 4; ++mi) {
#pragma unroll
                for (int h = 0; h < 2; ++h) {
                    int r = mi * 2 + h;
                    float d0 = eq.x - 2.0f * acc[mi][ni][h * 2];
                    float d1 = eq.y - 2.0f * acc[mi][ni][h * 2 + 1];
                    acc[mi][ni][h * 2] = 0.f; acc[mi][ni][h * 2 + 1] = 0.f;
                    int code = colbase + ni * 8;
                    if (d0 < bv[r]) { sv[r] = bv[r]; bv[r] = d0; bi[r] = code; }
                    else if (d0 < sv[r]) sv[r] = d0;
                    if (d1 < bv[r]) { sv[r] = bv[r]; bv[r] = d1; bi[r] = code + 1; }
                    else if (d1 < sv[r]) sv[r] = d1;
                }
            }
        }
    }

    // ---- cross-thread top-2 merge (16 owners per row) ----
    float* rbv = (float*)(dynsmem + 128 * XSTR * 2);
    float* rsv = rbv + 2048;
    int*   rbi = (int*)(rsv + 2048);
    __syncthreads();
#pragma unroll
    for (int mi = 0; mi < 4; ++mi)
#pragma unroll
        for (int h = 0; h < 2; ++h) {
            int row  = warp_m * 64 + mi * 16 + (l >> 2) + 8 * h;
            int slot = warp_n * 4 + (l & 3);
            rbv[row * 16 + slot] = bv[mi * 2 + h];
            rsv[row * 16 + slot] = sv[mi * 2 + h];
            rbi[row * 16 + slot] = bi[mi * 2 + h];
        }
    __syncthreads();
    if (tid < 128) {
        float b1 = FLT_MAX, s1 = FLT_MAX; int i1 = 0;
#pragma unroll
        for (int t = 0; t < 16; ++t) {
            float b2 = rbv[tid * 16 + t], s2 = rsv[tid * 16 + t];
            int   i2 = rbi[tid * 16 + t];
            if (b2 < b1) { s1 = fminf(b1, s2); b1 = b2; i1 = i2; }
            else         { s1 = fminf(s1, b2); }
        }
        int grow = row0 + tid;
        g_best[grow] = i1;
        if (s1 - b1 < MARGIN) {
            int s = atomicAdd(&g_nflag, 1);
            g_flag[s] = grow;
            g_bestkey[grow] = 0xFFFFFFFFFFFFFFFFull;
        }
    }
}

// ---------------------------------------------------------------------------
// rescue: exact fp32 rescore of flagged rows, split over 64 code chunks
// ---------------------------------------------------------------------------
#define ESL 33
#define RESCUE_SMEM ((BM*DIM + BN*ESL + BN + BM*16) * 4 + (BM*16) * 4 + BM * 4)

__global__ __launch_bounds__(256, 1)
void rescue_kernel(const float* __restrict__ x, const float* __restrict__ embed) {
    const int nf = g_nflag;
    const int base = blockIdx.x * BM;
    if (base >= nf) return;
    const int code0 = blockIdx.y * BN;

    float* xs      = (float*)dynsmem;
    float* es      = xs + BM * DIM;
    float* esq_s   = es + BN * ESL;
    float* red_val = esq_s + BN;
    int*   red_idx = (int*)(red_val + BM * 16);
    int*   rows_l  = red_idx + BM * 16;

    const int tid = threadIdx.x;
    const int ty = tid >> 4, tx = tid & 15;

    if (tid < BM) {
        int s = base + tid;
        rows_l[tid] = g_flag[(s < nf) ? s : base];
    }
    if (tid < BN) esq_s[tid] = g_esq[code0 + tid];
    __syncthreads();

#pragma unroll 4
    for (int i = 0; i < 32; ++i) {
        int lin = i * 256 + tid;
        int row = lin >> 6, q = lin & 63;
        ((float4*)(xs + row * DIM))[q] =
            ((const float4*)(x + (size_t)rows_l[row] * DIM))[q];
    }

    float best_val[8]; int best_idx[8];
#pragma unroll
    for (int i = 0; i < 8; ++i) { best_val[i] = FLT_MAX; best_idx[i] = 0; }

    float acc[8][8];
#pragma unroll
    for (int i = 0; i < 8; ++i)
#pragma unroll
        for (int j = 0; j < 8; ++j) acc[i][j] = 0.f;

    for (int cb = 0; cb < DIM / 32; ++cb) {
        __syncthreads();
#pragma unroll
        for (int lgl = 0; lgl < 4; ++lgl) {
            int lin = tid + lgl * 256;
            int col = lin >> 3, q = lin & 7;
            float4 v = *(const float4*)(embed + (size_t)(code0 + col) * DIM + cb * 32 + q * 4);
            es[col * ESL + q * 4 + 0] = v.x;
            es[col * ESL + q * 4 + 1] = v.y;
            es[col * ESL + q * 4 + 2] = v.z;
            es[col * ESL + q * 4 + 3] = v.w;
        }
        __syncthreads();
        const float* xbase = xs + cb * 32;
#pragma unroll
        for (int kk = 0; kk < 32; ++kk) {
            float xr[8], er[8];
#pragma unroll
            for (int i = 0; i < 8; ++i) xr[i] = xbase[(ty + 16 * i) * DIM + kk];
#pragma unroll
            for (int j = 0; j < 8; ++j) er[j] = es[(tx + 16 * j) * ESL + kk];
#pragma unroll
            for (int i = 0; i < 8; ++i)
#pragma unroll
                for (int j = 0; j < 8; ++j)
                    acc[i][j] = fmaf(xr[i], er[j], acc[i][j]);
        }
    }
#pragma unroll
    for (int j = 0; j < 8; ++j) {
        int code = code0 + tx + 16 * j;
        float esq = esq_s[tx + 16 * j];
#pragma unroll
        for (int i = 0; i < 8; ++i) {
            float d = esq - 2.0f * acc[i][j];
            if (d < best_val[i] || (d == best_val[i] && code < best_idx[i])) {
                best_val[i] = d; best_idx[i] = code;
            }
        }
    }

    __syncthreads();
#pragma unroll
    for (int i = 0; i < 8; ++i) {
        int r = ty + 16 * i;
        red_val[r * 16 + tx] = best_val[i];
        red_idx[r * 16 + tx] = best_idx[i];
    }
    __syncthreads();
    if (tid < BM) {
        float bvv = red_val[tid * 16];
        int   bii = red_idx[tid * 16];
#pragma unroll
        for (int t = 1; t < 16; ++t) {
            float v = red_val[tid * 16 + t];
            int  ix = red_idx[tid * 16 + t];
            if (v < bvv || (v == bvv && ix < bii)) { bvv = v; bii = ix; }
        }
        atomicMin(&g_bestkey[rows_l[tid]], mkkey(bvv, bii));
    }
}

__global__ void finalize_kernel() {
    int s = blockIdx.x * blockDim.x + threadIdx.x;
    if (s < g_nflag) {
        int row = g_flag[s];
        g_best[row] = (int)(g_bestkey[row] & 0xffffffffu);
    }
}

__global__ void gather_kernel(const float* __restrict__ embed, float* __restrict__ out) {
    int row = blockIdx.x;
    int idx = g_best[row];
    const float4* src = (const float4*)(embed + (size_t)idx * DIM);
    float4*       dst = (float4*)(out + (size_t)row * DIM);
    dst[threadIdx.x] = src[threadIdx.x];
}

// ---------------------------------------------------------------------------
extern "C" void kernel_launch(void* const* d_in, const int* in_sizes, int n_in,
                              void* d_out, int out_size) {
    const float* x     = (const float*)d_in[0];
    const float* embed = (const float*)d_in[1];
    float*       out   = (float*)d_out;

    cudaFuncSetAttribute(argmin_hmma, cudaFuncAttributeMaxDynamicSharedMemorySize, MAIN_SMEM);
    cudaFuncSetAttribute(rescue_kernel, cudaFuncAttributeMaxDynamicSharedMemorySize, RESCUE_SMEM);

    split_kernel<<<2048, 256>>>(x, embed);
    esq_kernel<<<KCB, 32>>>(embed);
    argmin_hmma<<<NTOT / BM, 256, MAIN_SMEM>>>();
    rescue_kernel<<<dim3(NTOT / BM, KCB / BN), 256, RESCUE_SMEM>>>(x, embed);
    finalize_kernel<<<NTOT / 256, 256>>>();
    gather_kernel<<<NTOT, 64>>>(embed, out);
}

// round 6
// speedup vs baseline: 4.7302x; 1.2377x over previous
#include <cuda_runtime.h>
#include <cuda_fp16.h>
#include <cfloat>
#include <cstdint>

#define DIM   256
#define KCB   8192
#define NTOT  32768
#define BM    128
#define BN    128
#define MARGIN 0.25f

#define XSTR  264                      // padded half stride (conflict-free ldmatrix)
#define ES_BUF_BYTES (128 * XSTR * 2)
#define MAIN_SMEM (3 * 128 * XSTR * 2) // xs + 2 es buffers = 202752 B

// ---------------- device scratch ----------------
__device__ __align__(16) __half g_xh[NTOT * DIM];
__device__ __align__(16) __half g_eh[KCB * DIM];
__device__ float g_esq[KCB];
__device__ int   g_best[NTOT];
__device__ int   g_flag[NTOT];
__device__ unsigned long long g_bestkey[NTOT];
__device__ int   g_nflag;

extern __shared__ char dynsmem[];

__device__ __forceinline__ uint32_t smem_u32(const void* p) {
    uint32_t a;
    asm("{ .reg .u64 t; cvta.to.shared.u64 t, %1; cvt.u32.u64 %0, t; }" : "=r"(a) : "l"(p));
    return a;
}
__device__ __forceinline__ void cpa16(uint32_t dst, const void* src) {
    asm volatile("cp.async.cg.shared.global [%0], [%1], 16;" :: "r"(dst), "l"(src));
}
#define CP_COMMIT() asm volatile("cp.async.commit_group;" ::: "memory")
#define CP_WAIT1()  asm volatile("cp.async.wait_group 1;" ::: "memory")

__device__ __forceinline__ void ldmx4(uint32_t& r0, uint32_t& r1, uint32_t& r2, uint32_t& r3,
                                      uint32_t addr) {
    asm volatile("ldmatrix.sync.aligned.m8n8.x4.shared.b16 {%0,%1,%2,%3}, [%4];"
                 : "=r"(r0), "=r"(r1), "=r"(r2), "=r"(r3) : "r"(addr));
}
__device__ __forceinline__ void mma16816(float* c, const uint32_t* a, const uint32_t* b) {
    asm volatile("mma.sync.aligned.m16n8k16.row.col.f32.f16.f16.f32 "
                 "{%0,%1,%2,%3}, {%4,%5,%6,%7}, {%8,%9}, {%0,%1,%2,%3};"
                 : "+f"(c[0]), "+f"(c[1]), "+f"(c[2]), "+f"(c[3])
                 : "r"(a[0]), "r"(a[1]), "r"(a[2]), "r"(a[3]), "r"(b[0]), "r"(b[1]));
}
__device__ __forceinline__ unsigned long long mkkey(float f, int idx) {
    unsigned u = __float_as_uint(f);
    u = (u & 0x80000000u) ? ~u : (u | 0x80000000u);
    return ((unsigned long long)u << 32) | (unsigned)idx;
}

// ---------------------------------------------------------------------------
// fp32 -> fp16 conversion of x and embed; reset flag counter
// ---------------------------------------------------------------------------
__global__ void split_kernel(const float* __restrict__ x, const float* __restrict__ embed) {
    if (blockIdx.x == 0 && threadIdx.x == 0) g_nflag = 0;
    const int T1 = NTOT * DIM / 4, T2 = KCB * DIM / 4;
    int stride = gridDim.x * blockDim.x;
    for (int i = blockIdx.x * blockDim.x + threadIdx.x; i < T1 + T2; i += stride) {
        const float4* src; __half2* dst; int j;
        if (i < T1) { src = (const float4*)x;     dst = (__half2*)g_xh; j = i; }
        else        { src = (const float4*)embed; dst = (__half2*)g_eh; j = i - T1; }
        float4 v = src[j];
        dst[2 * j]     = __floats2half2_rn(v.x, v.y);
        dst[2 * j + 1] = __floats2half2_rn(v.z, v.w);
    }
}

__global__ void esq_kernel(const float* __restrict__ embed) {
    int k = blockIdx.x, lane = threadIdx.x;
    const float4* row = (const float4*)(embed + (size_t)k * DIM);
    float s = 0.f;
#pragma unroll
    for (int t = 0; t < 2; ++t) {
        float4 v = row[lane + 32 * t];
        s += v.x * v.x + v.y * v.y + v.z * v.z + v.w * v.w;
    }
#pragma unroll
    for (int o = 16; o; o >>= 1) s += __shfl_xor_sync(0xffffffffu, s, o);
    if (lane == 0) g_esq[k] = s;
}

// ---------------------------------------------------------------------------
// main: fp16 mma.sync argmin, 16 warps, warp tile 32x32, top-2 margin flagging
// ---------------------------------------------------------------------------
__global__ __launch_bounds__(512, 1) void argmin_hmma() {
    const uint32_t sb    = smem_u32(dynsmem);
    const uint32_t sb_xs = sb;
    const uint32_t sb_es = sb + 128 * XSTR * 2;

    const int tid = threadIdx.x;
    const int wid = tid >> 5, l = tid & 31;
    const int warp_m = wid >> 2, warp_n = wid & 3;   // 4 x 4 warps, 32x32 tiles
    const int row0 = blockIdx.x * BM;

    // ---- prologue: stage xs + es chunks 0,1 via cp.async ----
#pragma unroll
    for (int t = 0; t < 8; ++t) {                    // xs: 128 rows x 32 segs
        int lin = t * 512 + tid;
        int row = lin >> 5, seg = lin & 31;
        cpa16(sb_xs + (row * XSTR + seg * 8) * 2,
              g_xh + (size_t)(row0 + row) * DIM + seg * 8);
    }
#pragma unroll
    for (int t = 0; t < 8; ++t) {                    // es chunk 0 -> buf 0
        int lin = t * 512 + tid;
        int row = lin >> 5, seg = lin & 31;
        cpa16(sb_es + (row * XSTR + seg * 8) * 2,
              g_eh + (size_t)row * DIM + seg * 8);
    }
    CP_COMMIT();
#pragma unroll
    for (int t = 0; t < 8; ++t) {                    // es chunk 1 -> buf 1
        int lin = t * 512 + tid;
        int row = lin >> 5, seg = lin & 31;
        cpa16(sb_es + ES_BUF_BYTES + (row * XSTR + seg * 8) * 2,
              g_eh + (size_t)(128 + row) * DIM + seg * 8);
    }
    CP_COMMIT();

    // per-lane ldmatrix base addresses
    uint32_t a_base[2];
#pragma unroll
    for (int mi = 0; mi < 2; ++mi)
        a_base[mi] = sb_xs + ((warp_m * 32 + mi * 16 + (l & 15)) * XSTR + (l >> 4) * 8) * 2;
    const int bcode = (l & 7) + ((l >> 4) << 3);
    const int bkh   = (l >> 3) & 1;
    uint32_t b_base[2];
#pragma unroll
    for (int bt = 0; bt < 2; ++bt)
        b_base[bt] = sb_es + ((warp_n * 32 + bt * 16 + bcode) * XSTR + bkh * 8) * 2;

    float acc[2][4][4];
#pragma unroll
    for (int mi = 0; mi < 2; ++mi)
#pragma unroll
        for (int ni = 0; ni < 4; ++ni)
#pragma unroll
            for (int r = 0; r < 4; ++r) acc[mi][ni][r] = 0.f;

    float bv[4], sv[4];
    int   bi[4];
#pragma unroll
    for (int r = 0; r < 4; ++r) { bv[r] = FLT_MAX; sv[r] = FLT_MAX; bi[r] = 0; }

    for (int c = 0; c < KCB / BN; ++c) {
        CP_WAIT1();
        __syncthreads();
        const uint32_t bofs = (c & 1) ? ES_BUF_BYTES : 0;

#pragma unroll 4
        for (int kk = 0; kk < 16; ++kk) {
            uint32_t a[2][4], b[2][4];
#pragma unroll
            for (int mi = 0; mi < 2; ++mi)
                ldmx4(a[mi][0], a[mi][1], a[mi][2], a[mi][3], a_base[mi] + kk * 32);
#pragma unroll
            for (int bt = 0; bt < 2; ++bt)
                ldmx4(b[bt][0], b[bt][1], b[bt][2], b[bt][3], b_base[bt] + bofs + kk * 32);
#pragma unroll
            for (int mi = 0; mi < 2; ++mi) {
#pragma unroll
                for (int ni = 0; ni < 4; ++ni) {
                    uint32_t bf[2] = { b[ni >> 1][(ni & 1) * 2], b[ni >> 1][(ni & 1) * 2 + 1] };
                    mma16816(acc[mi][ni], a[mi], bf);
                }
            }
        }
        __syncthreads();
        if (c + 2 < KCB / BN) {                       // prefetch chunk c+2
#pragma unroll
            for (int t = 0; t < 8; ++t) {
                int lin = t * 512 + tid;
                int row = lin >> 5, seg = lin & 31;
                cpa16(sb_es + bofs + (row * XSTR + seg * 8) * 2,
                      g_eh + (size_t)((c + 2) * 128 + row) * DIM + seg * 8);
            }
        }
        CP_COMMIT();

        // ---- epilogue: distances + top-2 ----
        const int colbase = c * 128 + warp_n * 32 + (l & 3) * 2;
#pragma unroll
        for (int ni = 0; ni < 4; ++ni) {
            float2 eq = __ldg((const float2*)(g_esq + colbase + ni * 8));
#pragma unroll
            for (int mi = 0; mi < 2; ++mi) {
#pragma unroll
                for (int h = 0; h < 2; ++h) {
                    int r = mi * 2 + h;
                    float d0 = eq.x - 2.0f * acc[mi][ni][h * 2];
                    float d1 = eq.y - 2.0f * acc[mi][ni][h * 2 + 1];
                    acc[mi][ni][h * 2] = 0.f; acc[mi][ni][h * 2 + 1] = 0.f;
                    int code = colbase + ni * 8;
                    if (d0 < bv[r]) { sv[r] = bv[r]; bv[r] = d0; bi[r] = code; }
                    else if (d0 < sv[r]) sv[r] = d0;
                    if (d1 < bv[r]) { sv[r] = bv[r]; bv[r] = d1; bi[r] = code + 1; }
                    else if (d1 < sv[r]) sv[r] = d1;
                }
            }
        }
    }

    // ---- cross-thread top-2 merge (16 owners per row) ----
    float* rbv = (float*)(dynsmem + 128 * XSTR * 2);
    float* rsv = rbv + 2048;
    int*   rbi = (int*)(rsv + 2048);
    __syncthreads();
#pragma unroll
    for (int mi = 0; mi < 2; ++mi)
#pragma unroll
        for (int h = 0; h < 2; ++h) {
            int row  = warp_m * 32 + mi * 16 + (l >> 2) + 8 * h;
            int slot = warp_n * 4 + (l & 3);
            rbv[row * 16 + slot] = bv[mi * 2 + h];
            rsv[row * 16 + slot] = sv[mi * 2 + h];
            rbi[row * 16 + slot] = bi[mi * 2 + h];
        }
    __syncthreads();
    if (tid < 128) {
        float b1 = FLT_MAX, s1 = FLT_MAX; int i1 = 0;
#pragma unroll
        for (int t = 0; t < 16; ++t) {
            float b2 = rbv[tid * 16 + t], s2 = rsv[tid * 16 + t];
            int   i2 = rbi[tid * 16 + t];
            if (b2 < b1) { s1 = fminf(b1, s2); b1 = b2; i1 = i2; }
            else         { s1 = fminf(s1, b2); }
        }
        int grow = row0 + tid;
        g_best[grow] = i1;
        if (s1 - b1 < MARGIN) {
            int s = atomicAdd(&g_nflag, 1);
            g_flag[s] = grow;
            g_bestkey[grow] = 0xFFFFFFFFFFFFFFFFull;
        }
    }
}

// ---------------------------------------------------------------------------
// rescue: exact fp32 rescore of flagged rows, split over 64 code chunks
// ---------------------------------------------------------------------------
#define ESL 33
#define RESCUE_SMEM ((BM*DIM + BN*ESL + BN + BM*16) * 4 + (BM*16) * 4 + BM * 4)

__global__ __launch_bounds__(256, 1)
void rescue_kernel(const float* __restrict__ x, const float* __restrict__ embed) {
    const int nf = g_nflag;
    const int base = blockIdx.x * BM;
    if (base >= nf) return;
    const int code0 = blockIdx.y * BN;

    float* xs      = (float*)dynsmem;
    float* es      = xs + BM * DIM;
    float* esq_s   = es + BN * ESL;
    float* red_val = esq_s + BN;
    int*   red_idx = (int*)(red_val + BM * 16);
    int*   rows_l  = red_idx + BM * 16;

    const int tid = threadIdx.x;
    const int ty = tid >> 4, tx = tid & 15;

    if (tid < BM) {
        int s = base + tid;
        rows_l[tid] = g_flag[(s < nf) ? s : base];
    }
    if (tid < BN) esq_s[tid] = g_esq[code0 + tid];
    __syncthreads();

#pragma unroll 4
    for (int i = 0; i < 32; ++i) {
        int lin = i * 256 + tid;
        int row = lin >> 6, q = lin & 63;
        ((float4*)(xs + row * DIM))[q] =
            ((const float4*)(x + (size_t)rows_l[row] * DIM))[q];
    }

    float best_val[8]; int best_idx[8];
#pragma unroll
    for (int i = 0; i < 8; ++i) { best_val[i] = FLT_MAX; best_idx[i] = 0; }

    float acc[8][8];
#pragma unroll
    for (int i = 0; i < 8; ++i)
#pragma unroll
        for (int j = 0; j < 8; ++j) acc[i][j] = 0.f;

    for (int cb = 0; cb < DIM / 32; ++cb) {
        __syncthreads();
#pragma unroll
        for (int lgl = 0; lgl < 4; ++lgl) {
            int lin = tid + lgl * 256;
            int col = lin >> 3, q = lin & 7;
            float4 v = *(const float4*)(embed + (size_t)(code0 + col) * DIM + cb * 32 + q * 4);
            es[col * ESL + q * 4 + 0] = v.x;
            es[col * ESL + q * 4 + 1] = v.y;
            es[col * ESL + q * 4 + 2] = v.z;
            es[col * ESL + q * 4 + 3] = v.w;
        }
        __syncthreads();
        const float* xbase = xs + cb * 32;
#pragma unroll
        for (int kk = 0; kk < 32; ++kk) {
            float xr[8], er[8];
#pragma unroll
            for (int i = 0; i < 8; ++i) xr[i] = xbase[(ty + 16 * i) * DIM + kk];
#pragma unroll
            for (int j = 0; j < 8; ++j) er[j] = es[(tx + 16 * j) * ESL + kk];
#pragma unroll
            for (int i = 0; i < 8; ++i)
#pragma unroll
                for (int j = 0; j < 8; ++j)
                    acc[i][j] = fmaf(xr[i], er[j], acc[i][j]);
        }
    }
#pragma unroll
    for (int j = 0; j < 8; ++j) {
        int code = code0 + tx + 16 * j;
        float esq = esq_s[tx + 16 * j];
#pragma unroll
        for (int i = 0; i < 8; ++i) {
            float d = esq - 2.0f * acc[i][j];
            if (d < best_val[i] || (d == best_val[i] && code < best_idx[i])) {
                best_val[i] = d; best_idx[i] = code;
            }
        }
    }

    __syncthreads();
#pragma unroll
    for (int i = 0; i < 8; ++i) {
        int r = ty + 16 * i;
        red_val[r * 16 + tx] = best_val[i];
        red_idx[r * 16 + tx] = best_idx[i];
    }
    __syncthreads();
    if (tid < BM) {
        float bvv = red_val[tid * 16];
        int   bii = red_idx[tid * 16];
#pragma unroll
        for (int t = 1; t < 16; ++t) {
            float v = red_val[tid * 16 + t];
            int  ix = red_idx[tid * 16 + t];
            if (v < bvv || (v == bvv && ix < bii)) { bvv = v; bii = ix; }
        }
        atomicMin(&g_bestkey[rows_l[tid]], mkkey(bvv, bii));
    }
}

__global__ void finalize_kernel() {
    int s = blockIdx.x * blockDim.x + threadIdx.x;
    if (s < g_nflag) {
        int row = g_flag[s];
        g_best[row] = (int)(g_bestkey[row] & 0xffffffffu);
    }
}

__global__ void gather_kernel(const float* __restrict__ embed, float* __restrict__ out) {
    int row = blockIdx.x;
    int idx = g_best[row];
    const float4* src = (const float4*)(embed + (size_t)idx * DIM);
    float4*       dst = (float4*)(out + (size_t)row * DIM);
    dst[threadIdx.x] = src[threadIdx.x];
}

// ---------------------------------------------------------------------------
extern "C" void kernel_launch(void* const* d_in, const int* in_sizes, int n_in,
                              void* d_out, int out_size) {
    const float* x     = (const float*)d_in[0];
    const float* embed = (const float*)d_in[1];
    float*       out   = (float*)d_out;

    cudaFuncSetAttribute(argmin_hmma, cudaFuncAttributeMaxDynamicSharedMemorySize, MAIN_SMEM);
    cudaFuncSetAttribute(rescue_kernel, cudaFuncAttributeMaxDynamicSharedMemorySize, RESCUE_SMEM);

    split_kernel<<<2048, 256>>>(x, embed);
    esq_kernel<<<KCB, 32>>>(embed);
    argmin_hmma<<<NTOT / BM, 512, MAIN_SMEM>>>();
    rescue_kernel<<<dim3(NTOT / BM, KCB / BN), 256, RESCUE_SMEM>>>(x, embed);
    finalize_kernel<<<NTOT / 256, 256>>>();
    gather_kernel<<<NTOT, 64>>>(embed, out);
}